// round 1
// baseline (speedup 1.0000x reference)
#include <cuda_runtime.h>
#include <cstdint>

// Problem constants (fixed by the reference)
#define DD 64            // embedding dim
#define KK 512           // num embeddings
#define KC 256           // K-chunk held in smem
#define ROWS 64          // rows per CTA
#define NTHREADS 256
#define NVEC 65536       // 64*32*32

// Device scratch (no cudaMalloc allowed)
__device__ float        g_wt[KK * DD];   // W transposed: [k][d], for coalesced code gather
__device__ float        g_c[KK];         // |w_k|^2
__device__ double       g_sse;           // sum of (q - x)^2
__device__ unsigned int g_hist[KK];      // code histogram

__device__ __forceinline__ void fma2(unsigned long long& d,
                                     unsigned long long a,
                                     unsigned long long b,
                                     unsigned long long c) {
    asm("fma.rn.f32x2 %0, %1, %2, %3;" : "=l"(d) : "l"(a), "l"(b), "l"(c));
}

// ---------------------------------------------------------------------------
// Prep: zero accumulators, compute |w_k|^2, transpose W -> Wt[k][d]
// grid = KK/128 blocks x 128 threads
// ---------------------------------------------------------------------------
__global__ void vq_prep(const float* __restrict__ w) {
    int k = blockIdx.x * 128 + threadIdx.x;
    if (k == 0) g_sse = 0.0;
    g_hist[k] = 0u;
    float s = 0.f;
#pragma unroll
    for (int d = 0; d < DD; d++) {
        float v = w[d * KK + k];   // coalesced across k
        s += v * v;
        g_wt[k * DD + d] = v;
    }
    g_c[k] = s;
}

// ---------------------------------------------------------------------------
// Main: per CTA 64 rows; loop K in 2 chunks of 256 via smem; per thread
// 8 rows x 8 cols register tile, f32x2-packed over adjacent k.
// warp = one 8-row group (tid>>5), lane = col-group (8 consecutive k's).
// ---------------------------------------------------------------------------
__global__ __launch_bounds__(NTHREADS, 2)
void vq_main(const float* __restrict__ x, const float* __restrict__ w,
             float* __restrict__ out_q, float* __restrict__ out_idx) {
    extern __shared__ float sm[];
    float* ws = sm;                 // [DD][KC]  64*256 floats = 64 KB
    float* xs = sm + DD * KC;       // [ROWS][DD] 64*64 floats = 16 KB

    const int tid  = threadIdx.x;
    const int warp = tid >> 5;      // 0..7  -> rows warp*8 .. warp*8+7
    const int lane = tid & 31;      // 0..31 -> cols lane*8 .. lane*8+7 (per chunk)
    const int rowBase = blockIdx.x * ROWS;

    // Load X tile (coalesced float4)
    {
        const float4* xin = (const float4*)(x + (size_t)rowBase * DD);
        float4* xs4 = (float4*)xs;
#pragma unroll
        for (int i = 0; i < (ROWS * DD / 4) / NTHREADS; i++)
            xs4[i * NTHREADS + tid] = xin[i * NTHREADS + tid];
    }

    float bestv[8];
    int   besti[8];
#pragma unroll
    for (int r = 0; r < 8; r++) { bestv[r] = -3.4e38f; besti[r] = 0; }

#pragma unroll 1
    for (int chunk = 0; chunk < KK / KC; chunk++) {
        const int kc = chunk * KC;
        __syncthreads();                       // protect ws reuse + first X pass
        // Load W chunk [DD][KC] (coalesced float4)
        {
            float4* ws4 = (float4*)ws;
#pragma unroll
            for (int i = 0; i < (DD * KC / 4) / NTHREADS; i++) {
                int idx = i * NTHREADS + tid;  // float4 index; 64 float4 per d-row
                int dd = idx >> 6, jj = idx & 63;
                ws4[idx] = *(const float4*)(w + dd * KK + kc + jj * 4);
            }
        }
        __syncthreads();

        const int k0 = kc + lane * 8;
        float cv[8];
#pragma unroll
        for (int j = 0; j < 8; j++) cv[j] = g_c[k0 + j];

        unsigned long long acc[8][4];
#pragma unroll
        for (int r = 0; r < 8; r++)
#pragma unroll
            for (int c = 0; c < 4; c++) acc[r][c] = 0ULL;

        const float* xrow = xs + warp * 8 * DD;
        const float* wcol = ws + lane * 8;

#pragma unroll 4
        for (int d = 0; d < DD; d++) {
            const ulonglong2* wp = (const ulonglong2*)(wcol + d * KC);
            ulonglong2 wA = wp[0];             // k pairs (0,1),(2,3)
            ulonglong2 wB = wp[1];             // k pairs (4,5),(6,7)
#pragma unroll
            for (int r = 0; r < 8; r++) {
                float xv = xrow[r * DD + d];   // warp-uniform -> LDS broadcast
                unsigned long long xx;
                asm("mov.b64 %0, {%1, %1};" : "=l"(xx) : "f"(xv));
                fma2(acc[r][0], xx, wA.x, acc[r][0]);
                fma2(acc[r][1], xx, wA.y, acc[r][1]);
                fma2(acc[r][2], xx, wB.x, acc[r][2]);
                fma2(acc[r][3], xx, wB.y, acc[r][3]);
            }
        }

        // Scores: argmax of (2*dot - |w|^2) == argmin distance; strict '>' keeps
        // the first (lowest-k) winner, matching jnp.argmax tie-break.
#pragma unroll
        for (int r = 0; r < 8; r++) {
#pragma unroll
            for (int c = 0; c < 4; c++) {
                float lo, hi;
                asm("mov.b64 {%0, %1}, %2;" : "=f"(lo), "=f"(hi) : "l"(acc[r][c]));
                float v0 = fmaf(2.f, lo, -cv[2 * c]);
                float v1 = fmaf(2.f, hi, -cv[2 * c + 1]);
                int kk = k0 + 2 * c;
                if (v0 > bestv[r]) { bestv[r] = v0; besti[r] = kk; }
                if (v1 > bestv[r]) { bestv[r] = v1; besti[r] = kk + 1; }
            }
        }
    }

    // Warp-wide argmax per row (min-index on ties)
#pragma unroll
    for (int r = 0; r < 8; r++) {
        float v = bestv[r];
        int   i = besti[r];
#pragma unroll
        for (int off = 16; off > 0; off >>= 1) {
            float v2 = __shfl_xor_sync(0xffffffffu, v, off);
            int   i2 = __shfl_xor_sync(0xffffffffu, i, off);
            if (v2 > v || (v2 == v && i2 < i)) { v = v2; i = i2; }
        }
        besti[r] = i;
    }

    // Epilogue: gather code (coalesced from Wt), straight-through output,
    // SSE partial, histogram, index output.
    float sse = 0.f;
#pragma unroll
    for (int r = 0; r < 8; r++) {
        const int row  = warp * 8 + r;
        const int grow = rowBase + row;
        const int kk   = besti[r];
        if (lane == 0) {
            atomicAdd(&g_hist[kk], 1u);
            out_idx[grow] = (float)kk;
        }
        float2 q  = *(const float2*)(g_wt + kk * DD + lane * 2);
        float2 xv = *(const float2*)(xs + row * DD + lane * 2);
        float d0 = q.x - xv.x, d1 = q.y - xv.y;
        float2 st;
        st.x = xv.x + d0;                     // replicate x + (q - x) rounding
        st.y = xv.y + d1;
        *(float2*)(out_q + (size_t)grow * DD + lane * 2) = st;
        sse += d0 * d0 + d1 * d1;
    }
#pragma unroll
    for (int off = 16; off > 0; off >>= 1)
        sse += __shfl_xor_sync(0xffffffffu, sse, off);
    if (lane == 0) atomicAdd(&g_sse, (double)sse);
}

// ---------------------------------------------------------------------------
// Finalize: loss + perplexity (1 block x 512 threads)
// ---------------------------------------------------------------------------
__global__ void vq_finalize(float* __restrict__ out_tail) {
    __shared__ float red[KK];
    int t = threadIdx.x;
    float p = (float)g_hist[t] / (float)NVEC;
    red[t] = -p * logf(p + 1e-10f);   // p==0 -> exactly 0, as in reference
    __syncthreads();
#pragma unroll
    for (int s = KK / 2; s > 0; s >>= 1) {
        if (t < s) red[t] += red[t + s];
        __syncthreads();
    }
    if (t == 0) {
        float m = (float)(g_sse / (double)((size_t)NVEC * DD));
        out_tail[0] = m + 0.25f * m;       // q_loss + COMMITMENT_COST * e_loss
        out_tail[1] = expf(red[0]);
    }
}

// ---------------------------------------------------------------------------
extern "C" void kernel_launch(void* const* d_in, const int* in_sizes, int n_in,
                              void* d_out, int out_size) {
    const float* x = (const float*)d_in[0];
    const float* w = (const float*)d_in[1];
    float* out = (float*)d_out;

    const int N = in_sizes[0] / DD;            // 65536
    const size_t ND = (size_t)N * DD;

    // Layout: [quantized_st (N*D) | loss | perplexity | indices (N)]
    float* out_q    = out;
    float* out_tail = out + ND;                // loss, perplexity
    float* out_idx  = out + ND + 2;

    const int smem_bytes = (DD * KC + ROWS * DD) * (int)sizeof(float);  // 80 KB
    cudaFuncSetAttribute(vq_main, cudaFuncAttributeMaxDynamicSharedMemorySize,
                         smem_bytes);

    vq_prep<<<KK / 128, 128>>>(w);
    vq_main<<<N / ROWS, NTHREADS, smem_bytes>>>(x, w, out_q, out_idx);
    vq_finalize<<<1, KK>>>(out_tail);
}